// round 12
// baseline (speedup 1.0000x reference)
#include <cuda_runtime.h>
#include <cuda_fp16.h>
#include <math.h>

#define N_NODES 100000
#define N_EDGES 3200000
#define FULL 0xffffffffu

// ---------------- static scratch (no allocation allowed) ----------------
__device__ unsigned int g_featH[N_NODES * 64]; // transformed feats, half-packed
__device__ unsigned int g_xH[N_NODES * 64];    // fp16 copy of layer-0 input
__device__ unsigned int g_hH[N_NODES * 64];    // fp16 layer-0 output
__device__ __half g_WH[2][128 * 128];          // fp16 weights
__device__ float g_el[N_NODES * 4];
__device__ float g_er[N_NODES * 4];
__device__ int   g_deg[N_NODES];
__device__ int   g_off[N_NODES + 1];
__device__ int   g_cur[N_NODES];
__device__ int2  g_edge_s[N_EDGES];            // {src, ew-bits} sorted by dst

// ---------------- conversions ----------------
__global__ void cvt_feat_kernel(const float4* __restrict__ x, uint2* __restrict__ y, int n32) {
    int i = blockIdx.x * blockDim.x + threadIdx.x;
    if (i < n32) {
        float4 v = x[i];
        __half2 a = __floats2half2_rn(v.x, v.y);
        __half2 b = __floats2half2_rn(v.z, v.w);
        y[i] = make_uint2(*(unsigned int*)&a, *(unsigned int*)&b);
    }
}

__global__ void cvt_w_kernel(const float* __restrict__ W0, const float* __restrict__ W1) {
    int i = blockIdx.x * blockDim.x + threadIdx.x;
    if (i < 128 * 128) {
        g_WH[0][i] = __float2half_rn(W0[i]);
        g_WH[1][i] = __float2half_rn(W1[i]);
    }
}

// ---------------- CSR build ----------------
__global__ void hist_kernel(const int* __restrict__ dst, int e) {
    int i = blockIdx.x * blockDim.x + threadIdx.x;
    if (i < e) atomicAdd(&g_deg[dst[i]], 1);
}

__global__ void scan_kernel(int n) {
    __shared__ int part[1024];
    int tid = threadIdx.x;
    int chunk = (n + 1023) / 1024;
    int b = tid * chunk;
    int e = min(b + chunk, n);
    int s = 0;
    for (int i = b; i < e; i++) s += g_deg[i];
    part[tid] = s;
    __syncthreads();
    for (int off = 1; off < 1024; off <<= 1) {
        int v = (tid >= off) ? part[tid - off] : 0;
        __syncthreads();
        part[tid] += v;
        __syncthreads();
    }
    int run = tid ? part[tid - 1] : 0;
    for (int i = b; i < e; i++) {
        g_off[i] = run;
        g_cur[i] = run;
        run += g_deg[i];
    }
    if (tid == 0) g_off[n] = part[1023];
}

__global__ void scatter_kernel(const int* __restrict__ src,
                               const int* __restrict__ dst,
                               const float* __restrict__ ew, int e) {
    int i = blockIdx.x * blockDim.x + threadIdx.x;
    if (i < e) {
        int p = atomicAdd(&g_cur[dst[i]], 1);
        g_edge_s[p] = make_int2(src[i], __float_as_int(ew[i]));
    }
}

// ---------------- tensor-core GEMM + fused el/er ----------------
__global__ __launch_bounds__(256) void gemm_mma_kernel(
    const unsigned int* __restrict__ aH,   // [n*64] u32 (half2), 128 halves/row
    const __half* __restrict__ wH,         // [128 k][128 n] row-major
    const float* __restrict__ al, const float* __restrict__ ar,
    unsigned int* __restrict__ featH, float* __restrict__ el,
    float* __restrict__ er, int n)
{
    __shared__ __align__(16) __half sW[128 * 128];
    int tid = threadIdx.x, lane = tid & 31, warp = tid >> 5;

    // stage W swizzled: 16B chunk (k, c) -> slot (k, c ^ (k&7))
    {
        const uint4* srcp = (const uint4*)wH;
        uint4* dstp = (uint4*)sW;
        #pragma unroll
        for (int i = tid; i < 2048; i += 256) {
            int k = i >> 4, c = i & 15;
            dstp[(k << 4) | (c ^ (k & 7))] = srcp[i];
        }
    }
    __syncthreads();

    int row0 = blockIdx.x * 128 + warp * 16;
    if (row0 >= n) return;   // n % 16 == 0, warp-granular guard

    float acc[64];
    #pragma unroll
    for (int i = 0; i < 64; i++) acc[i] = 0.f;

    int qr = lane >> 2;   // 0..7
    int qc = lane & 3;    // 0..3
    const unsigned int* aRow = aH + (size_t)(row0 + qr) * 64 + qc;

    unsigned int smemW = (unsigned int)__cvta_generic_to_shared(sW);
    int krow = (lane & 15);
    int cbase = (lane >> 4);

    #pragma unroll
    for (int ks = 0; ks < 8; ks++) {
        int k = ks * 16;
        unsigned int A0 = aRow[k / 2];
        unsigned int A1 = aRow[8 * 64 + k / 2];
        unsigned int A2 = aRow[k / 2 + 4];
        unsigned int A3 = aRow[8 * 64 + k / 2 + 4];

        int kr = k + krow;
        unsigned int rowAddr = smemW + kr * 256;
        int ksw = kr & 7;

        #pragma unroll
        for (int np = 0; np < 8; np++) {
            unsigned int b0, b1, b2, b3;
            int cn = np * 2 + cbase;
            unsigned int addr = rowAddr + (((unsigned)(cn ^ ksw)) << 4);
            asm volatile("ldmatrix.sync.aligned.m8n8.x4.trans.shared.b16 {%0,%1,%2,%3}, [%4];\n"
                : "=r"(b0), "=r"(b1), "=r"(b2), "=r"(b3) : "r"(addr));
            float* c = acc + np * 8;
            asm volatile("mma.sync.aligned.m16n8k16.row.col.f32.f16.f16.f32 "
                "{%0,%1,%2,%3},{%4,%5,%6,%7},{%8,%9},{%0,%1,%2,%3};\n"
                : "+f"(c[0]), "+f"(c[1]), "+f"(c[2]), "+f"(c[3])
                : "r"(A0), "r"(A1), "r"(A2), "r"(A3), "r"(b0), "r"(b1));
            asm volatile("mma.sync.aligned.m16n8k16.row.col.f32.f16.f16.f32 "
                "{%0,%1,%2,%3},{%4,%5,%6,%7},{%8,%9},{%0,%1,%2,%3};\n"
                : "+f"(c[4]), "+f"(c[5]), "+f"(c[6]), "+f"(c[7])
                : "r"(A0), "r"(A1), "r"(A2), "r"(A3), "r"(b2), "r"(b3));
        }
    }

    int ra = row0 + qr, rb = ra + 8;
    #pragma unroll
    for (int hd = 0; hd < 4; hd++) {
        float sla = 0.f, slb = 0.f, sra = 0.f, srb = 0.f;
        #pragma unroll
        for (int t = 0; t < 4; t++) {
            int np = hd * 2 + (t >> 1), blk = t & 1;
            int c0 = np * 16 + blk * 8 + qc * 2;
            float a0v = __ldg(&al[c0]), a1v = __ldg(&al[c0 + 1]);
            float r0v = __ldg(&ar[c0]), r1v = __ldg(&ar[c0 + 1]);
            float* c = acc + np * 8 + blk * 4;
            sla += c[0] * a0v + c[1] * a1v;
            slb += c[2] * a0v + c[3] * a1v;
            sra += c[0] * r0v + c[1] * r1v;
            srb += c[2] * r0v + c[3] * r1v;
        }
        sla += __shfl_xor_sync(FULL, sla, 1); sla += __shfl_xor_sync(FULL, sla, 2);
        slb += __shfl_xor_sync(FULL, slb, 1); slb += __shfl_xor_sync(FULL, slb, 2);
        sra += __shfl_xor_sync(FULL, sra, 1); sra += __shfl_xor_sync(FULL, sra, 2);
        srb += __shfl_xor_sync(FULL, srb, 1); srb += __shfl_xor_sync(FULL, srb, 2);
        if (qc == 0) {
            el[(size_t)ra * 4 + hd] = sla;
            el[(size_t)rb * 4 + hd] = slb;
            er[(size_t)ra * 4 + hd] = sra;
            er[(size_t)rb * 4 + hd] = srb;
        }
    }

    size_t ra64 = (size_t)ra * 64, rb64 = (size_t)rb * 64;
    #pragma unroll
    for (int np = 0; np < 8; np++) {
        #pragma unroll
        for (int blk = 0; blk < 2; blk++) {
            float* c = acc + np * 8 + blk * 4;
            __half2 ha = __floats2half2_rn(c[0], c[1]);
            __half2 hb = __floats2half2_rn(c[2], c[3]);
            int cu = np * 8 + blk * 4 + qc;
            featH[ra64 + cu] = *(unsigned int*)&ha;
            featH[rb64 + cu] = *(unsigned int*)&hb;
        }
    }
}

// ---------------- fused softmax + aggregation (single edge pass) ----------------
// Full 32-edge blocks run unpredicated with feature gathers double-buffered
// across the four 8-edge groups (prefetch group g+1 while FMA-ing group g).
__global__ __launch_bounds__(256) void aggregate_kernel(
    const unsigned int* __restrict__ featH, const float* __restrict__ el,
    const float* __restrict__ er, const float* __restrict__ bias,
    float* __restrict__ outF, unsigned int* __restrict__ outH,
    int writeHalf, int n)
{
    int warp = threadIdx.x >> 5;
    int lane = threadIdx.x & 31;
    int node = blockIdx.x * 8 + warp;
    if (node >= n) return;

    int beg = g_off[node];
    int end = g_off[node + 1];

    int hl    = lane >> 3;
    int sub   = lane & 7;
    int hbase = lane & 24;

    float er_h = __ldg(&er[(size_t)node * 4 + hl]);

    float  se  = 0.f;
    float4 acc = make_float4(0.f, 0.f, 0.f, 0.f);
    const uint2* featv = (const uint2*)featH;
    const int2*  edges = g_edge_s;

    int j = beg;
    int jfull = end - ((end - beg) & 31);

    // ---- full blocks: unpredicated, double-buffered gathers ----
    for (; j < jfull; j += 32) {
        int2 ed = edges[j + lane];
        int   sg[4];
        float wg[4], elg[4];
        #pragma unroll
        for (int g = 0; g < 4; g++) {
            sg[g] = __shfl_sync(FULL, ed.x, g * 8 + sub);
            wg[g] = __int_as_float(__shfl_sync(FULL, ed.y, g * 8 + sub));
        }
        #pragma unroll
        for (int g = 0; g < 4; g++)
            elg[g] = __ldg(&el[(size_t)sg[g] * 4 + hl]);

        uint2 fb0[8], fb1[8];
        // prefetch group 0
        #pragma unroll
        for (int t = 0; t < 8; t++) {
            int ss = __shfl_sync(FULL, sg[0], t);
            fb0[t] = featv[(size_t)ss * 32 + lane];
        }

        #pragma unroll
        for (int g = 0; g < 4; g++) {
            // prefetch next group into the alternate buffer
            if (g < 3) {
                if (g & 1) {
                    #pragma unroll
                    for (int t = 0; t < 8; t++) {
                        int ss = __shfl_sync(FULL, sg[g + 1], t);
                        fb0[t] = featv[(size_t)ss * 32 + lane];
                    }
                } else {
                    #pragma unroll
                    for (int t = 0; t < 8; t++) {
                        int ss = __shfl_sync(FULL, sg[g + 1], t);
                        fb1[t] = featv[(size_t)ss * 32 + lane];
                    }
                }
            }

            float v = elg[g] + er_h;
            v = v > 0.f ? v : 0.2f * v;
            v = fminf(v, 40.f);
            float ex = __expf(v);
            se += ex;
            float a = ex * wg[g];

            const uint2* fb = (g & 1) ? fb1 : fb0;
            #pragma unroll
            for (int t = 0; t < 8; t++) {
                float at = __shfl_sync(FULL, a, hbase | t);
                uint2 u  = fb[t];
                float2 f01 = __half22float2(*(__half2*)&u.x);
                float2 f23 = __half22float2(*(__half2*)&u.y);
                acc.x = fmaf(at, f01.x, acc.x);
                acc.y = fmaf(at, f01.y, acc.y);
                acc.z = fmaf(at, f23.x, acc.z);
                acc.w = fmaf(at, f23.y, acc.w);
            }
        }
    }

    // ---- tail block (< 32 edges) ----
    if (j < end) {
        int navail = end - j;
        int2 ed = (j + lane < end) ? edges[j + lane] : make_int2(0, 0);
        int   sg[4];
        float wg[4], elg[4];
        #pragma unroll
        for (int g = 0; g < 4; g++) {
            sg[g] = __shfl_sync(FULL, ed.x, g * 8 + sub);
            wg[g] = __int_as_float(__shfl_sync(FULL, ed.y, g * 8 + sub));
        }
        #pragma unroll
        for (int g = 0; g < 4; g++)
            elg[g] = __ldg(&el[(size_t)sg[g] * 4 + hl]);

        #pragma unroll
        for (int g = 0; g < 4; g++) {
            int base = g * 8;
            if (base >= navail) break;
            float v = elg[g] + er_h;
            v = v > 0.f ? v : 0.2f * v;
            v = fminf(v, 40.f);
            float ex = (base + sub < navail) ? __expf(v) : 0.f;
            se += ex;
            float a = ex * wg[g];
            int cnt = min(navail - base, 8);
            for (int t = 0; t < cnt; t++) {
                int   ss = __shfl_sync(FULL, sg[g], t);
                float at = __shfl_sync(FULL, a, hbase | t);
                uint2 u  = featv[(size_t)ss * 32 + lane];
                float2 f01 = __half22float2(*(__half2*)&u.x);
                float2 f23 = __half22float2(*(__half2*)&u.y);
                acc.x = fmaf(at, f01.x, acc.x);
                acc.y = fmaf(at, f01.y, acc.y);
                acc.z = fmaf(at, f23.x, acc.z);
                acc.w = fmaf(at, f23.y, acc.w);
            }
        }
    }

    se += __shfl_xor_sync(FULL, se, 1);
    se += __shfl_xor_sync(FULL, se, 2);
    se += __shfl_xor_sync(FULL, se, 4);
    float i_h = 1.f / fmaxf(se, 1e-20f);

    float4 b = ((const float4*)bias)[lane];
    float4 o;
    o.x = fmaf(acc.x, i_h, b.x); o.x = o.x > 0.f ? o.x : expm1f(o.x);
    o.y = fmaf(acc.y, i_h, b.y); o.y = o.y > 0.f ? o.y : expm1f(o.y);
    o.z = fmaf(acc.z, i_h, b.z); o.z = o.z > 0.f ? o.z : expm1f(o.z);
    o.w = fmaf(acc.w, i_h, b.w); o.w = o.w > 0.f ? o.w : expm1f(o.w);

    if (writeHalf) {
        __half2 h01 = __floats2half2_rn(o.x, o.y);
        __half2 h23 = __floats2half2_rn(o.z, o.w);
        ((uint2*)outH)[(size_t)node * 32 + lane] =
            make_uint2(*(unsigned int*)&h01, *(unsigned int*)&h23);
    } else {
        ((float4*)outF)[(size_t)node * 32 + lane] = o;
    }
}

// ---------------- launcher (single stream; overlap regressed in R11) ----------------
extern "C" void kernel_launch(void* const* d_in, const int* in_sizes, int n_in,
                              void* d_out, int out_size) {
    const float* in_feat = (const float*)d_in[0];
    const float* ew      = (const float*)d_in[1];
    const int*   src     = (const int*)d_in[2];
    const int*   dst     = (const int*)d_in[3];
    const float* W0      = (const float*)d_in[4];
    const float* al0     = (const float*)d_in[5];
    const float* ar0     = (const float*)d_in[6];
    const float* b0      = (const float*)d_in[7];
    const float* W1      = (const float*)d_in[8];
    const float* al1     = (const float*)d_in[9];
    const float* ar1     = (const float*)d_in[10];
    const float* b1      = (const float*)d_in[11];
    float* out = (float*)d_out;

    int N = in_sizes[0] / 128;
    int E = in_sizes[1];

    unsigned int *featH_p, *xH_p, *hH_p;
    float *el_p, *er_p;
    __half* wH_p;
    int* deg_p;
    cudaGetSymbolAddress((void**)&featH_p, g_featH);
    cudaGetSymbolAddress((void**)&xH_p,    g_xH);
    cudaGetSymbolAddress((void**)&hH_p,    g_hH);
    cudaGetSymbolAddress((void**)&el_p,    g_el);
    cudaGetSymbolAddress((void**)&er_p,    g_er);
    cudaGetSymbolAddress((void**)&wH_p,    g_WH);
    cudaGetSymbolAddress((void**)&deg_p,   g_deg);

    // CSR build (graph shared by both layers)
    cudaMemsetAsync(deg_p, 0, (size_t)N * sizeof(int));
    hist_kernel<<<(E + 255) / 256, 256>>>(dst, E);
    scan_kernel<<<1, 1024>>>(N);
    scatter_kernel<<<(E + 255) / 256, 256>>>(src, dst, ew, E);

    // fp16 conversions
    int n32 = N * 32;
    cvt_feat_kernel<<<(n32 + 255) / 256, 256>>>((const float4*)in_feat, (uint2*)xH_p, n32);
    cvt_w_kernel<<<(128 * 128 + 255) / 256, 256>>>(W0, W1);

    int gemm_blocks = (N + 127) / 128;
    int agg_blocks  = (N + 7) / 8;

    // layer 0
    gemm_mma_kernel<<<gemm_blocks, 256>>>(xH_p, wH_p, al0, ar0, featH_p, el_p, er_p, N);
    aggregate_kernel<<<agg_blocks, 256>>>(featH_p, el_p, er_p, b0, (float*)0, hH_p, 1, N);
    // layer 1
    gemm_mma_kernel<<<gemm_blocks, 256>>>(hH_p, wH_p + 128 * 128, al1, ar1, featH_p, el_p, er_p, N);
    aggregate_kernel<<<agg_blocks, 256>>>(featH_p, el_p, er_p, b1, out, (unsigned int*)0, 0, N);
}

// round 13
// speedup vs baseline: 1.1919x; 1.1919x over previous
#include <cuda_runtime.h>
#include <cuda_fp16.h>
#include <math.h>

#define N_NODES 100000
#define N_EDGES 3200000
#define FULL 0xffffffffu

// ---------------- static scratch (no allocation allowed) ----------------
__device__ unsigned int g_featH[N_NODES * 64]; // transformed feats, half-packed
__device__ unsigned int g_hH[N_NODES * 64];    // fp16 layer-0 output
__device__ float g_el[N_NODES * 4];
__device__ float g_er[N_NODES * 4];
__device__ int   g_deg[N_NODES];
__device__ int   g_off[N_NODES + 1];
__device__ int   g_cur[N_NODES];
__device__ int2  g_edge_s[N_EDGES];            // {src, ew-bits} sorted by dst

// ---------------- CSR build (4 edges per thread) ----------------
__global__ void hist_kernel(const int* __restrict__ dst, int e) {
    int i = (blockIdx.x * blockDim.x + threadIdx.x) * 4;
    if (i + 3 < e) {
        int4 d = *(const int4*)(dst + i);
        atomicAdd(&g_deg[d.x], 1);
        atomicAdd(&g_deg[d.y], 1);
        atomicAdd(&g_deg[d.z], 1);
        atomicAdd(&g_deg[d.w], 1);
    } else {
        for (int t = i; t < e; t++) atomicAdd(&g_deg[dst[t]], 1);
    }
}

__global__ void scan_kernel(int n) {
    __shared__ int part[1024];
    int tid = threadIdx.x;
    int chunk = (n + 1023) / 1024;
    int b = tid * chunk;
    int e = min(b + chunk, n);
    int s = 0;
    for (int i = b; i < e; i++) s += g_deg[i];
    part[tid] = s;
    __syncthreads();
    for (int off = 1; off < 1024; off <<= 1) {
        int v = (tid >= off) ? part[tid - off] : 0;
        __syncthreads();
        part[tid] += v;
        __syncthreads();
    }
    int run = tid ? part[tid - 1] : 0;
    for (int i = b; i < e; i++) {
        g_off[i] = run;
        g_cur[i] = run;
        run += g_deg[i];
    }
    if (tid == 0) g_off[n] = part[1023];
}

__global__ void scatter_kernel(const int* __restrict__ src,
                               const int* __restrict__ dst,
                               const float* __restrict__ ew, int e) {
    int i = (blockIdx.x * blockDim.x + threadIdx.x) * 4;
    if (i + 3 < e) {
        int4   s = *(const int4*)(src + i);
        int4   d = *(const int4*)(dst + i);
        float4 w = *(const float4*)(ew + i);
        int p0 = atomicAdd(&g_cur[d.x], 1);
        int p1 = atomicAdd(&g_cur[d.y], 1);
        int p2 = atomicAdd(&g_cur[d.z], 1);
        int p3 = atomicAdd(&g_cur[d.w], 1);
        g_edge_s[p0] = make_int2(s.x, __float_as_int(w.x));
        g_edge_s[p1] = make_int2(s.y, __float_as_int(w.y));
        g_edge_s[p2] = make_int2(s.z, __float_as_int(w.z));
        g_edge_s[p3] = make_int2(s.w, __float_as_int(w.w));
    } else {
        for (int t = i; t < e; t++) {
            int p = atomicAdd(&g_cur[dst[t]], 1);
            g_edge_s[p] = make_int2(src[t], __float_as_int(ew[t]));
        }
    }
}

// ---------------- A-fragment loaders (overloaded on input type) ----------------
__device__ __forceinline__ void load_a_frag(
    const __half* aIn, size_t row, int qc, int k,
    unsigned int& A0, unsigned int& A1, unsigned int& A2, unsigned int& A3)
{
    const unsigned int* aRow = (const unsigned int*)aIn + row * 64 + qc;
    A0 = aRow[k / 2];
    A1 = aRow[8 * 64 + k / 2];
    A2 = aRow[k / 2 + 4];
    A3 = aRow[8 * 64 + k / 2 + 4];
}

__device__ __forceinline__ void load_a_frag(
    const float* aIn, size_t row, int qc, int k,
    unsigned int& A0, unsigned int& A1, unsigned int& A2, unsigned int& A3)
{
    const float2* aRow = (const float2*)aIn + row * 64 + qc;
    float2 f0 = aRow[k / 2];
    float2 f1 = aRow[8 * 64 + k / 2];
    float2 f2 = aRow[k / 2 + 4];
    float2 f3 = aRow[8 * 64 + k / 2 + 4];
    __half2 h0 = __floats2half2_rn(f0.x, f0.y);
    __half2 h1 = __floats2half2_rn(f1.x, f1.y);
    __half2 h2 = __floats2half2_rn(f2.x, f2.y);
    __half2 h3 = __floats2half2_rn(f3.x, f3.y);
    A0 = *(unsigned int*)&h0;
    A1 = *(unsigned int*)&h1;
    A2 = *(unsigned int*)&h2;
    A3 = *(unsigned int*)&h3;
}

// ---------------- tensor-core GEMM + fused el/er ----------------
// A input either fp32 (layer 0, converted in-register) or fp16 (layer 1).
// W is fp32, converted to half during swizzled smem staging.
template <typename AT>
__global__ __launch_bounds__(256) void gemm_mma_kernel(
    const AT* __restrict__ aIn,
    const float* __restrict__ wF,          // [128 k][128 n] row-major fp32
    const float* __restrict__ al, const float* __restrict__ ar,
    unsigned int* __restrict__ featH, float* __restrict__ el,
    float* __restrict__ er, int n)
{
    __shared__ __align__(16) __half sW[128 * 128];
    int tid = threadIdx.x, lane = tid & 31, warp = tid >> 5;

    // stage W: fp32 -> half, swizzled 16B chunks (k, c) -> (k, c ^ (k&7))
    {
        const float4* srcp = (const float4*)wF;
        uint4* dstp = (uint4*)sW;
        #pragma unroll
        for (int i = tid; i < 2048; i += 256) {
            int k = i >> 4, c = i & 15;
            float4 fa = srcp[i * 2];
            float4 fb = srcp[i * 2 + 1];
            __half2 h0 = __floats2half2_rn(fa.x, fa.y);
            __half2 h1 = __floats2half2_rn(fa.z, fa.w);
            __half2 h2 = __floats2half2_rn(fb.x, fb.y);
            __half2 h3 = __floats2half2_rn(fb.z, fb.w);
            uint4 u;
            u.x = *(unsigned int*)&h0; u.y = *(unsigned int*)&h1;
            u.z = *(unsigned int*)&h2; u.w = *(unsigned int*)&h3;
            dstp[(k << 4) | (c ^ (k & 7))] = u;
        }
    }
    __syncthreads();

    int row0 = blockIdx.x * 128 + warp * 16;
    if (row0 >= n) return;   // n % 16 == 0, warp-granular guard

    float acc[64];
    #pragma unroll
    for (int i = 0; i < 64; i++) acc[i] = 0.f;

    int qr = lane >> 2;   // 0..7
    int qc = lane & 3;    // 0..3
    size_t rowA = (size_t)(row0 + qr);

    unsigned int smemW = (unsigned int)__cvta_generic_to_shared(sW);
    int krow = (lane & 15);
    int cbase = (lane >> 4);

    #pragma unroll
    for (int ks = 0; ks < 8; ks++) {
        int k = ks * 16;
        unsigned int A0, A1, A2, A3;
        load_a_frag(aIn, rowA, qc, k, A0, A1, A2, A3);

        int kr = k + krow;
        unsigned int rowAddr = smemW + kr * 256;
        int ksw = kr & 7;

        #pragma unroll
        for (int np = 0; np < 8; np++) {
            unsigned int b0, b1, b2, b3;
            int cn = np * 2 + cbase;
            unsigned int addr = rowAddr + (((unsigned)(cn ^ ksw)) << 4);
            asm volatile("ldmatrix.sync.aligned.m8n8.x4.trans.shared.b16 {%0,%1,%2,%3}, [%4];\n"
                : "=r"(b0), "=r"(b1), "=r"(b2), "=r"(b3) : "r"(addr));
            float* c = acc + np * 8;
            asm volatile("mma.sync.aligned.m16n8k16.row.col.f32.f16.f16.f32 "
                "{%0,%1,%2,%3},{%4,%5,%6,%7},{%8,%9},{%0,%1,%2,%3};\n"
                : "+f"(c[0]), "+f"(c[1]), "+f"(c[2]), "+f"(c[3])
                : "r"(A0), "r"(A1), "r"(A2), "r"(A3), "r"(b0), "r"(b1));
            asm volatile("mma.sync.aligned.m16n8k16.row.col.f32.f16.f16.f32 "
                "{%0,%1,%2,%3},{%4,%5,%6,%7},{%8,%9},{%0,%1,%2,%3};\n"
                : "+f"(c[4]), "+f"(c[5]), "+f"(c[6]), "+f"(c[7])
                : "r"(A0), "r"(A1), "r"(A2), "r"(A3), "r"(b2), "r"(b3));
        }
    }

    int ra = row0 + qr, rb = ra + 8;
    #pragma unroll
    for (int hd = 0; hd < 4; hd++) {
        float sla = 0.f, slb = 0.f, sra = 0.f, srb = 0.f;
        #pragma unroll
        for (int t = 0; t < 4; t++) {
            int np = hd * 2 + (t >> 1), blk = t & 1;
            int c0 = np * 16 + blk * 8 + qc * 2;
            float a0v = __ldg(&al[c0]), a1v = __ldg(&al[c0 + 1]);
            float r0v = __ldg(&ar[c0]), r1v = __ldg(&ar[c0 + 1]);
            float* c = acc + np * 8 + blk * 4;
            sla += c[0] * a0v + c[1] * a1v;
            slb += c[2] * a0v + c[3] * a1v;
            sra += c[0] * r0v + c[1] * r1v;
            srb += c[2] * r0v + c[3] * r1v;
        }
        sla += __shfl_xor_sync(FULL, sla, 1); sla += __shfl_xor_sync(FULL, sla, 2);
        slb += __shfl_xor_sync(FULL, slb, 1); slb += __shfl_xor_sync(FULL, slb, 2);
        sra += __shfl_xor_sync(FULL, sra, 1); sra += __shfl_xor_sync(FULL, sra, 2);
        srb += __shfl_xor_sync(FULL, srb, 1); srb += __shfl_xor_sync(FULL, srb, 2);
        if (qc == 0) {
            el[(size_t)ra * 4 + hd] = sla;
            el[(size_t)rb * 4 + hd] = slb;
            er[(size_t)ra * 4 + hd] = sra;
            er[(size_t)rb * 4 + hd] = srb;
        }
    }

    size_t ra64 = (size_t)ra * 64, rb64 = (size_t)rb * 64;
    #pragma unroll
    for (int np = 0; np < 8; np++) {
        #pragma unroll
        for (int blk = 0; blk < 2; blk++) {
            float* c = acc + np * 8 + blk * 4;
            __half2 ha = __floats2half2_rn(c[0], c[1]);
            __half2 hb = __floats2half2_rn(c[2], c[3]);
            int cu = np * 8 + blk * 4 + qc;
            featH[ra64 + cu] = *(unsigned int*)&ha;
            featH[rb64 + cu] = *(unsigned int*)&hb;
        }
    }
}

// ---------------- fused softmax + aggregation (R10 version, verbatim) ----------------
__global__ __launch_bounds__(256) void aggregate_kernel(
    const unsigned int* __restrict__ featH, const float* __restrict__ el,
    const float* __restrict__ er, const float* __restrict__ bias,
    float* __restrict__ outF, unsigned int* __restrict__ outH,
    int writeHalf, int n)
{
    int warp = threadIdx.x >> 5;
    int lane = threadIdx.x & 31;
    int node = blockIdx.x * 8 + warp;
    if (node >= n) return;

    int beg = g_off[node];
    int end = g_off[node + 1];

    int hl    = lane >> 3;
    int sub   = lane & 7;
    int hbase = lane & 24;

    float er_h = __ldg(&er[(size_t)node * 4 + hl]);

    float  se  = 0.f;
    float4 acc = make_float4(0.f, 0.f, 0.f, 0.f);
    const uint2* featv = (const uint2*)featH;
    const int2*  edges = g_edge_s;

    for (int j = beg; j < end; j += 32) {
        int navail = end - j;
        int2 ed = (j + lane < end) ? edges[j + lane] : make_int2(0, 0);

        int   sg[4];
        float wg[4];
        float elg[4];
        #pragma unroll
        for (int g = 0; g < 4; g++) {
            sg[g] = __shfl_sync(FULL, ed.x, g * 8 + sub);
            wg[g] = __int_as_float(__shfl_sync(FULL, ed.y, g * 8 + sub));
        }
        #pragma unroll
        for (int g = 0; g < 4; g++)
            elg[g] = __ldg(&el[(size_t)sg[g] * 4 + hl]);

        #pragma unroll
        for (int g = 0; g < 4; g++) {
            int base = g * 8;
            if (base >= navail) break;
            float v = elg[g] + er_h;
            v = v > 0.f ? v : 0.2f * v;
            v = fminf(v, 40.f);
            float ex = (base + sub < navail) ? __expf(v) : 0.f;
            se += ex;
            float a = ex * wg[g];
            int cnt = navail - base;
            if (cnt >= 8) {
                #pragma unroll
                for (int t = 0; t < 8; t++) {
                    int   ss = __shfl_sync(FULL, sg[g], t);
                    float at = __shfl_sync(FULL, a, hbase | t);
                    uint2 u  = featv[(size_t)ss * 32 + lane];
                    float2 f01 = __half22float2(*(__half2*)&u.x);
                    float2 f23 = __half22float2(*(__half2*)&u.y);
                    acc.x = fmaf(at, f01.x, acc.x);
                    acc.y = fmaf(at, f01.y, acc.y);
                    acc.z = fmaf(at, f23.x, acc.z);
                    acc.w = fmaf(at, f23.y, acc.w);
                }
            } else {
                for (int t = 0; t < cnt; t++) {
                    int   ss = __shfl_sync(FULL, sg[g], t);
                    float at = __shfl_sync(FULL, a, hbase | t);
                    uint2 u  = featv[(size_t)ss * 32 + lane];
                    float2 f01 = __half22float2(*(__half2*)&u.x);
                    float2 f23 = __half22float2(*(__half2*)&u.y);
                    acc.x = fmaf(at, f01.x, acc.x);
                    acc.y = fmaf(at, f01.y, acc.y);
                    acc.z = fmaf(at, f23.x, acc.z);
                    acc.w = fmaf(at, f23.y, acc.w);
                }
            }
        }
    }

    se += __shfl_xor_sync(FULL, se, 1);
    se += __shfl_xor_sync(FULL, se, 2);
    se += __shfl_xor_sync(FULL, se, 4);
    float i_h = 1.f / fmaxf(se, 1e-20f);

    float4 b = ((const float4*)bias)[lane];
    float4 o;
    o.x = fmaf(acc.x, i_h, b.x); o.x = o.x > 0.f ? o.x : expm1f(o.x);
    o.y = fmaf(acc.y, i_h, b.y); o.y = o.y > 0.f ? o.y : expm1f(o.y);
    o.z = fmaf(acc.z, i_h, b.z); o.z = o.z > 0.f ? o.z : expm1f(o.z);
    o.w = fmaf(acc.w, i_h, b.w); o.w = o.w > 0.f ? o.w : expm1f(o.w);

    if (writeHalf) {
        __half2 h01 = __floats2half2_rn(o.x, o.y);
        __half2 h23 = __floats2half2_rn(o.z, o.w);
        ((uint2*)outH)[(size_t)node * 32 + lane] =
            make_uint2(*(unsigned int*)&h01, *(unsigned int*)&h23);
    } else {
        ((float4*)outF)[(size_t)node * 32 + lane] = o;
    }
}

// ---------------- launcher (single stream) ----------------
extern "C" void kernel_launch(void* const* d_in, const int* in_sizes, int n_in,
                              void* d_out, int out_size) {
    const float* in_feat = (const float*)d_in[0];
    const float* ew      = (const float*)d_in[1];
    const int*   src     = (const int*)d_in[2];
    const int*   dst     = (const int*)d_in[3];
    const float* W0      = (const float*)d_in[4];
    const float* al0     = (const float*)d_in[5];
    const float* ar0     = (const float*)d_in[6];
    const float* b0      = (const float*)d_in[7];
    const float* W1      = (const float*)d_in[8];
    const float* al1     = (const float*)d_in[9];
    const float* ar1     = (const float*)d_in[10];
    const float* b1      = (const float*)d_in[11];
    float* out = (float*)d_out;

    int N = in_sizes[0] / 128;
    int E = in_sizes[1];

    unsigned int *featH_p, *hH_p;
    float *el_p, *er_p;
    int* deg_p;
    cudaGetSymbolAddress((void**)&featH_p, g_featH);
    cudaGetSymbolAddress((void**)&hH_p,    g_hH);
    cudaGetSymbolAddress((void**)&el_p,    g_el);
    cudaGetSymbolAddress((void**)&er_p,    g_er);
    cudaGetSymbolAddress((void**)&deg_p,   g_deg);

    // CSR build (graph shared by both layers)
    int e4threads = (E + 3) / 4;
    cudaMemsetAsync(deg_p, 0, (size_t)N * sizeof(int));
    hist_kernel<<<(e4threads + 255) / 256, 256>>>(dst, E);
    scan_kernel<<<1, 1024>>>(N);
    scatter_kernel<<<(e4threads + 255) / 256, 256>>>(src, dst, ew, E);

    int gemm_blocks = (N + 127) / 128;
    int agg_blocks  = (N + 7) / 8;

    // layer 0 (fp32 A input, conversions fused into GEMM)
    gemm_mma_kernel<float><<<gemm_blocks, 256>>>(in_feat, W0, al0, ar0, featH_p, el_p, er_p, N);
    aggregate_kernel<<<agg_blocks, 256>>>(featH_p, el_p, er_p, b0, (float*)0, hH_p, 1, N);
    // layer 1 (fp16 A input from aggregate 0)
    gemm_mma_kernel<__half><<<gemm_blocks, 256>>>((const __half*)hH_p, W1, al1, ar1, featH_p, el_p, er_p, N);
    aggregate_kernel<<<agg_blocks, 256>>>(featH_p, el_p, er_p, b1, out, (unsigned int*)0, 0, N);
}